// round 2
// baseline (speedup 1.0000x reference)
#include <cuda_runtime.h>
#include <math.h>

// Problem dims (B=1)
#define LEN   3072
#define HID   3072
#define NH    24
#define HD    128
#define MLPD  12288
#define N1    (3*HID + MLPD)   // 21504  (lin1 out)
#define N2    (HID + MLPD)     // 15360  (lin2 in)
#define EPSF  1e-6f

// ---------------- scratch (static device allocs; no cudaMalloc allowed) ----
__device__ float g_sv[HID];                       // silu(vec)
__device__ float g_mod[3*HID];                    // shift|scale|gate
__device__ float g_xmod[(size_t)LEN*HID];         // modulated LN output
__device__ float g_proj[(size_t)LEN*N1];          // lin1 output (264 MB)
__device__ float g_q[(size_t)NH*LEN*HD];
__device__ float g_k[(size_t)NH*LEN*HD];
__device__ float g_v[(size_t)NH*LEN*HD];
__device__ float g_S[(size_t)NH*LEN*LEN];         // logits / probs (906 MB)
__device__ float g_attn[(size_t)NH*LEN*HD];
__device__ float g_cat[(size_t)LEN*N2];           // [attn | gelu(mlp)] (189 MB)

// ---------------- small elementwise kernels --------------------------------
__global__ void silu_kernel(const float* __restrict__ vec) {
    int i = blockIdx.x * blockDim.x + threadIdx.x;
    if (i < HID) {
        float v = vec[i];
        g_sv[i] = v / (1.f + __expf(-v));
    }
}

// mod[j] = dot(silu(vec), mod_w[j,:]) + mod_b[j]   (one warp per j)
__global__ void gemv_mod_kernel(const float* __restrict__ W, const float* __restrict__ b) {
    int j = blockIdx.x * 8 + (threadIdx.x >> 5);
    int lane = threadIdx.x & 31;
    const float4* w4 = (const float4*)(W + (size_t)j * HID);
    const float4* s4 = (const float4*)g_sv;
    float acc = 0.f;
    for (int i = lane; i < HID/4; i += 32) {
        float4 w = w4[i], s = s4[i];
        acc += w.x*s.x + w.y*s.y + w.z*s.z + w.w*s.w;
    }
    #pragma unroll
    for (int o = 16; o; o >>= 1) acc += __shfl_xor_sync(0xffffffffu, acc, o);
    if (lane == 0) g_mod[j] = acc + b[j];
}

// LayerNorm + modulation: x_mod = LN(x)*(1+scale) + shift. One block per row.
__global__ void layernorm_kernel(const float* __restrict__ x) {
    __shared__ float shA[8], shB[8];
    __shared__ float s_mu, s_r;
    int l = blockIdx.x, t = threadIdx.x;
    const float* row = x + (size_t)l * HID;
    float v[12];
    float s = 0.f, ss = 0.f;
    #pragma unroll
    for (int i = 0; i < 12; i++) {
        v[i] = row[t + i*256];
        s += v[i]; ss += v[i]*v[i];
    }
    #pragma unroll
    for (int o = 16; o; o >>= 1) {
        s  += __shfl_xor_sync(0xffffffffu, s,  o);
        ss += __shfl_xor_sync(0xffffffffu, ss, o);
    }
    if ((t & 31) == 0) { shA[t>>5] = s; shB[t>>5] = ss; }
    __syncthreads();
    if (t == 0) {
        float a = 0.f, bb = 0.f;
        #pragma unroll
        for (int w = 0; w < 8; w++) { a += shA[w]; bb += shB[w]; }
        float mu = a / HID;
        float var = bb / HID - mu*mu;
        s_mu = mu; s_r = rsqrtf(var + EPSF);
    }
    __syncthreads();
    float mu = s_mu, r = s_r;
    float* orow = g_xmod + (size_t)l * HID;
    #pragma unroll
    for (int i = 0; i < 12; i++) {
        int kcol = t + i*256;
        orow[kcol] = (v[i] - mu) * r * (1.f + g_mod[HID + kcol]) + g_mod[kcol];
    }
}

// ---------------- generic 128x128x8 tiled SGEMM ----------------------------
// C[M,N] = alpha * A[M,K] * op(B) + bias;  BT=1: B is [N,K] row-major (NT)
//                                          BT=0: B is [K,N] row-major (NN)
// All of M,N divisible by 128; K divisible by 8; pointers 16B-aligned.
template<int BT>
__global__ void __launch_bounds__(256) gemm_kernel(
    const float* __restrict__ A, const float* __restrict__ B,
    const float* __restrict__ bias, float* __restrict__ C,
    int M, int N, int K, float alpha,
    size_t sA, size_t sB, size_t sC)
{
    __shared__ float As[8][128];
    __shared__ float Bs[8][128];
    A += (size_t)blockIdx.z * sA;
    B += (size_t)blockIdx.z * sB;
    C += (size_t)blockIdx.z * sC;
    int tid = threadIdx.x;
    int m0 = blockIdx.y * 128, n0 = blockIdx.x * 128;
    int tx = tid & 15, ty = tid >> 4;
    int a_m = tid >> 1, a_k = (tid & 1) * 4;

    float acc[8][8];
    #pragma unroll
    for (int i = 0; i < 8; i++)
        #pragma unroll
        for (int j = 0; j < 8; j++) acc[i][j] = 0.f;

    for (int kt = 0; kt < K; kt += 8) {
        float4 av = *(const float4*)(A + (size_t)(m0 + a_m) * K + kt + a_k);
        As[a_k+0][a_m] = av.x; As[a_k+1][a_m] = av.y;
        As[a_k+2][a_m] = av.z; As[a_k+3][a_m] = av.w;
        if (BT) {
            float4 bv = *(const float4*)(B + (size_t)(n0 + a_m) * K + kt + a_k);
            Bs[a_k+0][a_m] = bv.x; Bs[a_k+1][a_m] = bv.y;
            Bs[a_k+2][a_m] = bv.z; Bs[a_k+3][a_m] = bv.w;
        } else {
            int b_k = tid >> 5, b_n = (tid & 31) * 4;
            float4 bv = *(const float4*)(B + (size_t)(kt + b_k) * N + n0 + b_n);
            *(float4*)&Bs[b_k][b_n] = bv;
        }
        __syncthreads();
        #pragma unroll
        for (int kk = 0; kk < 8; kk++) {
            float a[8], b[8];
            *(float4*)(a)     = *(const float4*)&As[kk][ty*8];
            *(float4*)(a + 4) = *(const float4*)&As[kk][ty*8 + 4];
            *(float4*)(b)     = *(const float4*)&Bs[kk][tx*8];
            *(float4*)(b + 4) = *(const float4*)&Bs[kk][tx*8 + 4];
            #pragma unroll
            for (int i = 0; i < 8; i++)
                #pragma unroll
                for (int j = 0; j < 8; j++)
                    acc[i][j] += a[i] * b[j];
        }
        __syncthreads();
    }

    #pragma unroll
    for (int i = 0; i < 8; i++) {
        int row = m0 + ty*8 + i;
        #pragma unroll
        for (int j = 0; j < 8; j += 4) {
            int col = n0 + tx*8 + j;
            float4 o;
            o.x = alpha * acc[i][j+0] + (bias ? bias[col+0] : 0.f);
            o.y = alpha * acc[i][j+1] + (bias ? bias[col+1] : 0.f);
            o.z = alpha * acc[i][j+2] + (bias ? bias[col+2] : 0.f);
            o.w = alpha * acc[i][j+3] + (bias ? bias[col+3] : 0.f);
            *(float4*)(C + (size_t)row * N + col) = o;
        }
    }
}

// ---------------- qkv split + RMS + RoPE -----------------------------------
// one warp per (h,l); lane owns d = lane*4..lane*4+3 (rope pairs stay in-thread)
__global__ void qkv_prep_kernel(const float* __restrict__ pe,
                                const float* __restrict__ q_scale,
                                const float* __restrict__ k_scale) {
    int w = threadIdx.x >> 5, lane = threadIdx.x & 31;
    int r = blockIdx.x * 8 + w;          // 0 .. NH*LEN-1
    int h = r / LEN, l = r % LEN;
    const float* prow = g_proj + (size_t)l * N1;
    float4 q4 = *(const float4*)(prow +            h*HD + lane*4);
    float4 k4 = *(const float4*)(prow +   HID    + h*HD + lane*4);
    float4 v4 = *(const float4*)(prow + 2*HID    + h*HD + lane*4);

    float qs = q4.x*q4.x + q4.y*q4.y + q4.z*q4.z + q4.w*q4.w;
    float ks = k4.x*k4.x + k4.y*k4.y + k4.z*k4.z + k4.w*k4.w;
    #pragma unroll
    for (int o = 16; o; o >>= 1) {
        qs += __shfl_xor_sync(0xffffffffu, qs, o);
        ks += __shfl_xor_sync(0xffffffffu, ks, o);
    }
    float qr = rsqrtf(qs / HD + EPSF);
    float kr = rsqrtf(ks / HD + EPSF);
    float4 qsc = *(const float4*)(q_scale + lane*4);
    float4 ksc = *(const float4*)(k_scale + lane*4);
    float tq[4] = { q4.x*qr*qsc.x, q4.y*qr*qsc.y, q4.z*qr*qsc.z, q4.w*qr*qsc.w };
    float tk[4] = { k4.x*kr*ksc.x, k4.y*kr*ksc.y, k4.z*kr*ksc.z, k4.w*kr*ksc.w };

    // pe layout: [l][i][j][c] -> l*256 + i*4 + j*2 + c;  i = lane*2 + p
    const float* peb = pe + (size_t)l * 256 + lane * 8;
    float4 oq, ok;
    oq.x = peb[0]*tq[0] + peb[1]*tq[1];
    oq.y = peb[2]*tq[0] + peb[3]*tq[1];
    oq.z = peb[4]*tq[2] + peb[5]*tq[3];
    oq.w = peb[6]*tq[2] + peb[7]*tq[3];
    ok.x = peb[0]*tk[0] + peb[1]*tk[1];
    ok.y = peb[2]*tk[0] + peb[3]*tk[1];
    ok.z = peb[4]*tk[2] + peb[5]*tk[3];
    ok.w = peb[6]*tk[2] + peb[7]*tk[3];

    size_t base = ((size_t)h * LEN + l) * HD + lane * 4;
    *(float4*)(g_q + base) = oq;
    *(float4*)(g_k + base) = ok;
    *(float4*)(g_v + base) = v4;
}

// ---------------- softmax over rows of g_S ---------------------------------
__global__ void softmax_kernel() {
    __shared__ float shA[8];
    __shared__ float s_bc;
    size_t row = blockIdx.x;             // h*LEN + q
    float* p = g_S + row * (size_t)LEN;
    int t = threadIdx.x;
    float x[12];
    float mx = -1e30f;
    #pragma unroll
    for (int i = 0; i < 12; i++) { x[i] = p[t + i*256]; mx = fmaxf(mx, x[i]); }
    #pragma unroll
    for (int o = 16; o; o >>= 1) mx = fmaxf(mx, __shfl_xor_sync(0xffffffffu, mx, o));
    if ((t & 31) == 0) shA[t>>5] = mx;
    __syncthreads();
    if (t == 0) {
        float m = shA[0];
        #pragma unroll
        for (int w = 1; w < 8; w++) m = fmaxf(m, shA[w]);
        s_bc = m;
    }
    __syncthreads();
    mx = s_bc;
    float s = 0.f;
    #pragma unroll
    for (int i = 0; i < 12; i++) { x[i] = __expf(x[i] - mx); s += x[i]; }
    #pragma unroll
    for (int o = 16; o; o >>= 1) s += __shfl_xor_sync(0xffffffffu, s, o);
    __syncthreads();
    if ((t & 31) == 0) shA[t>>5] = s;
    __syncthreads();
    if (t == 0) {
        float a = 0.f;
        #pragma unroll
        for (int w = 0; w < 8; w++) a += shA[w];
        s_bc = 1.f / a;
    }
    __syncthreads();
    float inv = s_bc;
    #pragma unroll
    for (int i = 0; i < 12; i++) p[t + i*256] = x[i] * inv;
}

// ---------------- cat = [attn (h,l,d -> l,h*D+d) | gelu(mlp_in)] ------------
__global__ void pack_cat_kernel() {
    size_t idx = (size_t)blockIdx.x * blockDim.x + threadIdx.x;
    if (idx >= (size_t)LEN * N2) return;
    int l = (int)(idx / N2);
    int c = (int)(idx % N2);
    float val;
    if (c < HID) {
        int h = c / HD, d = c % HD;
        val = g_attn[((size_t)h * LEN + l) * HD + d];
    } else {
        float xx = g_proj[(size_t)l * N1 + 3*HID + (c - HID)];
        float inner = 0.7978845608028654f * (xx + 0.044715f * xx * xx * xx);
        val = 0.5f * xx * (1.f + tanhf(inner));
    }
    g_cat[idx] = val;
}

// ---------------- final: out = x + gate * (y)  (y already has bias) --------
__global__ void final_kernel(const float* __restrict__ x, float* __restrict__ out) {
    size_t idx = (size_t)blockIdx.x * blockDim.x + threadIdx.x;
    if (idx >= (size_t)LEN * HID) return;
    int col = (int)(idx % HID);
    out[idx] = x[idx] + g_mod[2*HID + col] * out[idx];
}

// ---------------- launcher --------------------------------------------------
extern "C" void kernel_launch(void* const* d_in, const int* in_sizes, int n_in,
                              void* d_out, int out_size) {
    const float* x       = (const float*)d_in[0];
    const float* vec     = (const float*)d_in[1];
    const float* pe      = (const float*)d_in[2];
    const float* mod_w   = (const float*)d_in[3];
    const float* mod_b   = (const float*)d_in[4];
    const float* lin1_w  = (const float*)d_in[5];
    const float* lin1_b  = (const float*)d_in[6];
    const float* lin2_w  = (const float*)d_in[7];
    const float* lin2_b  = (const float*)d_in[8];
    const float* q_scale = (const float*)d_in[9];
    const float* k_scale = (const float*)d_in[10];
    float* out = (float*)d_out;

    void *p_xmod, *p_proj, *p_q, *p_k, *p_v, *p_S, *p_attn, *p_cat;
    cudaGetSymbolAddress(&p_xmod, g_xmod);
    cudaGetSymbolAddress(&p_proj, g_proj);
    cudaGetSymbolAddress(&p_q, g_q);
    cudaGetSymbolAddress(&p_k, g_k);
    cudaGetSymbolAddress(&p_v, g_v);
    cudaGetSymbolAddress(&p_S, g_S);
    cudaGetSymbolAddress(&p_attn, g_attn);
    cudaGetSymbolAddress(&p_cat, g_cat);

    // 1) silu(vec)
    silu_kernel<<<(HID + 255)/256, 256>>>(vec);
    // 2) mod = silu(vec) @ mod_w.T + mod_b
    gemv_mod_kernel<<<(3*HID)/8, 256>>>(mod_w, mod_b);
    // 3) LN + modulation
    layernorm_kernel<<<LEN, 256>>>(x);
    // 4) proj = x_mod @ lin1_w.T + lin1_b    (3072 x 21504 x 3072, NT)
    gemm_kernel<1><<<dim3(N1/128, LEN/128, 1), 256>>>(
        (const float*)p_xmod, lin1_w, lin1_b, (float*)p_proj,
        LEN, N1, HID, 1.f, 0, 0, 0);
    // 5) qkv split + RMS + RoPE
    qkv_prep_kernel<<<(NH*LEN)/8, 256>>>(pe, q_scale, k_scale);
    // 6) logits = q @ k.T / sqrt(D)          (per head, NT, K=128)
    gemm_kernel<1><<<dim3(LEN/128, LEN/128, NH), 256>>>(
        (const float*)p_q, (const float*)p_k, nullptr, (float*)p_S,
        LEN, LEN, HD, 0.08838834764831845f,
        (size_t)LEN*HD, (size_t)LEN*HD, (size_t)LEN*LEN);
    // 7) softmax rows
    softmax_kernel<<<NH*LEN, 256>>>();
    // 8) attn = P @ V                        (per head, NN, N=128)
    gemm_kernel<0><<<dim3(1, LEN/128, NH), 256>>>(
        (const float*)p_S, (const float*)p_v, nullptr, (float*)p_attn,
        LEN, HD, LEN, 1.f,
        (size_t)LEN*LEN, (size_t)LEN*HD, (size_t)LEN*HD);
    // 9) cat = [attn | gelu(mlp_in)]
    {
        size_t tot = (size_t)LEN * N2;
        pack_cat_kernel<<<(unsigned)((tot + 255)/256), 256>>>();
    }
    // 10) y = cat @ lin2_w.T + lin2_b -> d_out  (3072 x 3072 x 15360, NT)
    gemm_kernel<1><<<dim3(HID/128, LEN/128, 1), 256>>>(
        (const float*)p_cat, lin2_w, lin2_b, out,
        LEN, HID, N2, 1.f, 0, 0, 0);
    // 11) out = x + gate * y
    {
        size_t tot = (size_t)LEN * HID;
        final_kernel<<<(unsigned)((tot + 255)/256), 256>>>(x, out);
    }
}

// round 4
// speedup vs baseline: 2.5445x; 2.5445x over previous
#include <cuda_runtime.h>
#include <cuda_bf16.h>
#include <math.h>
#include <stdint.h>

#define LEN   3072
#define HID   3072
#define NH    24
#define HD    128
#define MLPD  12288
#define N1    (3*HID + MLPD)   // 21504
#define N2    (HID + MLPD)     // 15360
#define K1S   (3*HID)          // 9216  (tripled K for lin1)
#define K2S   (3*N2)           // 46080 (tripled K for lin2)
#define KQS   (3*HD)           // 384   (tripled K for qk)
#define EPSF  1e-6f

// ---------------- scratch ----------------------------------------------------
__device__ float g_sv[HID];
__device__ float g_mod[3*HID];
__device__ __align__(256) float g_proj[(size_t)LEN*N1];
__device__ __align__(256) __nv_bfloat16 g_a1[(size_t)LEN*K1S];
__device__ __align__(256) __nv_bfloat16 g_b1[(size_t)N1*K1S];
__device__ __align__(256) __nv_bfloat16 g_a2[(size_t)LEN*K2S];
__device__ __align__(256) __nv_bfloat16 g_b2[(size_t)HID*K2S];
__device__ __align__(256) __nv_bfloat16 g_qb[(size_t)NH*LEN*KQS];
__device__ __align__(256) __nv_bfloat16 g_kb[(size_t)NH*LEN*KQS];
__device__ __align__(256) __nv_bfloat16 g_vT[(size_t)NH*HD*LEN];
__device__ __align__(256) float g_S[(size_t)NH*LEN*LEN];
__device__ __align__(256) __nv_bfloat16 g_P[(size_t)NH*LEN*LEN];
__device__ __align__(256) float g_attn[(size_t)NH*LEN*HD];

__device__ __forceinline__ uint32_t smem_u32(const void* p) {
    uint32_t a;
    asm("{ .reg .u64 t; cvta.to.shared.u64 t, %1; cvt.u32.u64 %0, t; }" : "=r"(a) : "l"(p));
    return a;
}

// ---------------- HMMA GEMM --------------------------------------------------
// C[m,n] = alpha * sum_k A[m,k]*B[n,k] (+bias). A,B bf16 K-major row stride K.
// BM=BN=128, BK=32, 3-stage cp.async, 8 warps (4M x 2N), warp tile 32x64.
#define PITCH 80                      // 64B data + 16B pad per 32-k row
#define ATILE (128*PITCH)             // 10240 B
#define STGSZ (2*ATILE)               // 20480 B per stage
#define NSTG  3

__global__ void __launch_bounds__(256, 2) gemm_hmma(
    const __nv_bfloat16* __restrict__ A, const __nv_bfloat16* __restrict__ B,
    const float* __restrict__ bias, float* __restrict__ C,
    int ldC, int K, float alpha, size_t sA, size_t sB, size_t sC)
{
    extern __shared__ char smem[];
    const uint32_t sb = smem_u32(smem);
    const int tid = threadIdx.x, lane = tid & 31, wid = tid >> 5;
    const int wm = wid & 3, wn = wid >> 2;           // warp coords: 4 x 2
    const int m0 = blockIdx.x * 128, n0 = blockIdx.y * 128;
    A += (size_t)blockIdx.z * sA;
    B += (size_t)blockIdx.z * sB;
    C += (size_t)blockIdx.z * sC;
    const int KT = K >> 5;

    // cp.async assignment: idx 0..1023 -> 16B chunk
    // idx<512: A row=idx>>2 ch=idx&3 ; else B likewise
    auto load_stage = [&](int buf, int kt) {
        const int k0 = kt << 5;
        #pragma unroll
        for (int i = 0; i < 4; i++) {
            int idx = tid + (i << 8);
            int isB = idx >> 9;
            int r = (idx & 511) >> 2, ch = idx & 3;
            const __nv_bfloat16* src = (isB ? B + (size_t)(n0 + r) * K
                                            : A + (size_t)(m0 + r) * K) + k0 + ch * 8;
            uint32_t dst = sb + buf * STGSZ + isB * ATILE + r * PITCH + ch * 16;
            asm volatile("cp.async.cg.shared.global [%0], [%1], 16;"
                         :: "r"(dst), "l"(src) : "memory");
        }
    };

    float acc[2][8][4];
    #pragma unroll
    for (int a = 0; a < 2; a++)
        #pragma unroll
        for (int b = 0; b < 8; b++)
            #pragma unroll
            for (int c = 0; c < 4; c++) acc[a][b][c] = 0.f;

    // ldmatrix per-lane source rows/cols
    const int aRow = (lane & 7) + ((lane >> 3) & 1) * 8, aK = (lane >> 4) * 16;
    const int bRow = (lane & 7) + (lane >> 4) * 8,       bK = ((lane >> 3) & 1) * 16;
    const uint32_t aAdr0 = (uint32_t)((wm * 32 + aRow) * PITCH + aK);
    const uint32_t bAdr0 = (uint32_t)(ATILE + (wn * 64 + bRow) * PITCH + bK);

    load_stage(0, 0);
    asm volatile("cp.async.commit_group;" ::: "memory");
    if (KT > 1) load_stage(1, 1);
    asm volatile("cp.async.commit_group;" ::: "memory");

    for (int kt = 0; kt < KT; kt++) {
        asm volatile("cp.async.wait_group 1;" ::: "memory");
        __syncthreads();
        int nk = kt + 2;
        if (nk < KT) load_stage(nk % NSTG, nk);
        asm volatile("cp.async.commit_group;" ::: "memory");

        const uint32_t base = sb + (kt % NSTG) * STGSZ;
        #pragma unroll
        for (int ks = 0; ks < 2; ks++) {
            uint32_t ra[2][4], rb[4][4];
            #pragma unroll
            for (int mt = 0; mt < 2; mt++) {
                uint32_t ad = base + aAdr0 + mt * (16 * PITCH) + ks * 32;
                asm volatile("ldmatrix.sync.aligned.m8n8.x4.shared.b16 {%0,%1,%2,%3}, [%4];"
                    : "=r"(ra[mt][0]), "=r"(ra[mt][1]), "=r"(ra[mt][2]), "=r"(ra[mt][3])
                    : "r"(ad));
            }
            #pragma unroll
            for (int nt = 0; nt < 4; nt++) {
                uint32_t bd = base + bAdr0 + nt * (16 * PITCH) + ks * 32;
                asm volatile("ldmatrix.sync.aligned.m8n8.x4.shared.b16 {%0,%1,%2,%3}, [%4];"
                    : "=r"(rb[nt][0]), "=r"(rb[nt][1]), "=r"(rb[nt][2]), "=r"(rb[nt][3])
                    : "r"(bd));
            }
            #pragma unroll
            for (int mt = 0; mt < 2; mt++)
                #pragma unroll
                for (int nt = 0; nt < 4; nt++) {
                    #pragma unroll
                    for (int h = 0; h < 2; h++) {
                        float* c = acc[mt][nt * 2 + h];
                        asm volatile(
                            "mma.sync.aligned.m16n8k16.row.col.f32.bf16.bf16.f32 "
                            "{%0,%1,%2,%3}, {%4,%5,%6,%7}, {%8,%9}, {%0,%1,%2,%3};"
                            : "+f"(c[0]), "+f"(c[1]), "+f"(c[2]), "+f"(c[3])
                            : "r"(ra[mt][0]), "r"(ra[mt][1]), "r"(ra[mt][2]), "r"(ra[mt][3]),
                              "r"(rb[nt][h * 2]), "r"(rb[nt][h * 2 + 1]));
                    }
                }
        }
        __syncthreads();
    }

    // epilogue
    const int g = lane >> 2, tig = lane & 3;
    #pragma unroll
    for (int mt = 0; mt < 2; mt++) {
        #pragma unroll
        for (int j = 0; j < 8; j++) {
            int row = m0 + wm * 32 + mt * 16 + g;
            int col = n0 + wn * 64 + j * 8 + tig * 2;
            float b0 = bias ? bias[col] : 0.f, b1 = bias ? bias[col + 1] : 0.f;
            float2 v0 = { alpha * acc[mt][j][0] + b0, alpha * acc[mt][j][1] + b1 };
            float2 v1 = { alpha * acc[mt][j][2] + b0, alpha * acc[mt][j][3] + b1 };
            *(float2*)(C + (size_t)row * ldC + col) = v0;
            *(float2*)(C + (size_t)(row + 8) * ldC + col) = v1;
        }
    }
}

// ---------------- elementwise ------------------------------------------------
__device__ __forceinline__ void split2(float a, __nv_bfloat16& h, __nv_bfloat16& lo) {
    h = __float2bfloat16(a);
    lo = __float2bfloat16(a - __bfloat162float(h));
}

__global__ void silu_kernel(const float* __restrict__ vec) {
    int i = blockIdx.x * blockDim.x + threadIdx.x;
    if (i < HID) { float v = vec[i]; g_sv[i] = v / (1.f + __expf(-v)); }
}

__global__ void gemv_mod_kernel(const float* __restrict__ W, const float* __restrict__ b) {
    int j = blockIdx.x * 8 + (threadIdx.x >> 5);
    int lane = threadIdx.x & 31;
    const float4* w4 = (const float4*)(W + (size_t)j * HID);
    const float4* s4 = (const float4*)g_sv;
    float acc = 0.f;
    for (int i = lane; i < HID/4; i += 32) {
        float4 w = w4[i], s = s4[i];
        acc += w.x*s.x + w.y*s.y + w.z*s.z + w.w*s.w;
    }
    #pragma unroll
    for (int o = 16; o; o >>= 1) acc += __shfl_xor_sync(0xffffffffu, acc, o);
    if (lane == 0) g_mod[j] = acc + b[j];
}

// LN + modulation -> triple-split bf16 A operand (h,h,lo)
__global__ void layernorm_kernel(const float* __restrict__ x) {
    __shared__ float shA[8], shB[8];
    __shared__ float s_mu, s_r;
    int l = blockIdx.x, t = threadIdx.x;
    const float* row = x + (size_t)l * HID;
    float v[12];
    float s = 0.f, ss = 0.f;
    #pragma unroll
    for (int i = 0; i < 12; i++) { v[i] = row[t + i*256]; s += v[i]; ss += v[i]*v[i]; }
    #pragma unroll
    for (int o = 16; o; o >>= 1) {
        s  += __shfl_xor_sync(0xffffffffu, s, o);
        ss += __shfl_xor_sync(0xffffffffu, ss, o);
    }
    if ((t & 31) == 0) { shA[t>>5] = s; shB[t>>5] = ss; }
    __syncthreads();
    if (t == 0) {
        float a = 0.f, bb = 0.f;
        #pragma unroll
        for (int w = 0; w < 8; w++) { a += shA[w]; bb += shB[w]; }
        float mu = a / HID;
        s_mu = mu; s_r = rsqrtf(bb / HID - mu*mu + EPSF);
    }
    __syncthreads();
    float mu = s_mu, r = s_r;
    __nv_bfloat16* orow = g_a1 + (size_t)l * K1S;
    #pragma unroll
    for (int i = 0; i < 12; i++) {
        int kc = t + i*256;
        float xm = (v[i] - mu) * r * (1.f + g_mod[HID + kc]) + g_mod[kc];
        __nv_bfloat16 h, lo; split2(xm, h, lo);
        orow[3*kc] = h; orow[3*kc+1] = h; orow[3*kc+2] = lo;
    }
}

// weight split: B pattern (h, lo, h)
__global__ void conv_w(const float* __restrict__ src, __nv_bfloat16* __restrict__ dst, size_t n) {
    size_t i = (size_t)blockIdx.x * blockDim.x + threadIdx.x;
    if (i >= n) return;
    __nv_bfloat16 h, lo; split2(src[i], h, lo);
    size_t o = i * 3;
    dst[o] = h; dst[o+1] = lo; dst[o+2] = h;
}

// qkv split + RMS + RoPE; q,k -> tripled bf16 (K'=384); v -> transposed bf16
__global__ void qkv_prep_kernel(const float* __restrict__ pe,
                                const float* __restrict__ q_scale,
                                const float* __restrict__ k_scale) {
    int w = threadIdx.x >> 5, lane = threadIdx.x & 31;
    int rr = blockIdx.x * 8 + w;
    int h = rr / LEN, l = rr % LEN;
    const float* prow = g_proj + (size_t)l * N1;
    float4 q4 = *(const float4*)(prow +          h*HD + lane*4);
    float4 k4 = *(const float4*)(prow + HID    + h*HD + lane*4);
    float4 v4 = *(const float4*)(prow + 2*HID  + h*HD + lane*4);
    float qs = q4.x*q4.x + q4.y*q4.y + q4.z*q4.z + q4.w*q4.w;
    float ks = k4.x*k4.x + k4.y*k4.y + k4.z*k4.z + k4.w*k4.w;
    #pragma unroll
    for (int o = 16; o; o >>= 1) {
        qs += __shfl_xor_sync(0xffffffffu, qs, o);
        ks += __shfl_xor_sync(0xffffffffu, ks, o);
    }
    float qr = rsqrtf(qs / HD + EPSF), kr = rsqrtf(ks / HD + EPSF);
    float4 qsc = *(const float4*)(q_scale + lane*4);
    float4 ksc = *(const float4*)(k_scale + lane*4);
    float tq[4] = { q4.x*qr*qsc.x, q4.y*qr*qsc.y, q4.z*qr*qsc.z, q4.w*qr*qsc.w };
    float tk[4] = { k4.x*kr*ksc.x, k4.y*kr*ksc.y, k4.z*kr*ksc.z, k4.w*kr*ksc.w };
    const float* peb = pe + (size_t)l * 256 + lane * 8;
    float oq[4], ok[4];
    oq[0] = peb[0]*tq[0] + peb[1]*tq[1];
    oq[1] = peb[2]*tq[0] + peb[3]*tq[1];
    oq[2] = peb[4]*tq[2] + peb[5]*tq[3];
    oq[3] = peb[6]*tq[2] + peb[7]*tq[3];
    ok[0] = peb[0]*tk[0] + peb[1]*tk[1];
    ok[1] = peb[2]*tk[0] + peb[3]*tk[1];
    ok[2] = peb[4]*tk[2] + peb[5]*tk[3];
    ok[3] = peb[6]*tk[2] + peb[7]*tk[3];
    size_t qb = ((size_t)h * LEN + l) * KQS + lane * 12;
    float vv[4] = { v4.x, v4.y, v4.z, v4.w };
    #pragma unroll
    for (int j = 0; j < 4; j++) {
        __nv_bfloat16 hh, lo;
        split2(oq[j], hh, lo);
        g_qb[qb + 3*j] = hh; g_qb[qb + 3*j + 1] = hh; g_qb[qb + 3*j + 2] = lo;   // A: h,h,lo
        split2(ok[j], hh, lo);
        g_kb[qb + 3*j] = hh; g_kb[qb + 3*j + 1] = lo; g_kb[qb + 3*j + 2] = hh;   // B: h,lo,h
        g_vT[((size_t)h * HD + lane*4 + j) * LEN + l] = __float2bfloat16(vv[j]);
    }
}

// softmax rows of g_S -> bf16 probs g_P
__global__ void softmax_kernel() {
    __shared__ float shA[8];
    __shared__ float s_bc;
    size_t row = blockIdx.x;
    const float* p = g_S + row * (size_t)LEN;
    __nv_bfloat16* po = g_P + row * (size_t)LEN;
    int t = threadIdx.x;
    float x[12];
    float mx = -1e30f;
    #pragma unroll
    for (int i = 0; i < 12; i++) { x[i] = p[t + i*256]; mx = fmaxf(mx, x[i]); }
    #pragma unroll
    for (int o = 16; o; o >>= 1) mx = fmaxf(mx, __shfl_xor_sync(0xffffffffu, mx, o));
    if ((t & 31) == 0) shA[t>>5] = mx;
    __syncthreads();
    if (t == 0) {
        float m = shA[0];
        #pragma unroll
        for (int w = 1; w < 8; w++) m = fmaxf(m, shA[w]);
        s_bc = m;
    }
    __syncthreads();
    mx = s_bc;
    float s = 0.f;
    #pragma unroll
    for (int i = 0; i < 12; i++) { x[i] = __expf(x[i] - mx); s += x[i]; }
    #pragma unroll
    for (int o = 16; o; o >>= 1) s += __shfl_xor_sync(0xffffffffu, s, o);
    __syncthreads();
    if ((t & 31) == 0) shA[t>>5] = s;
    __syncthreads();
    if (t == 0) {
        float a = 0.f;
        #pragma unroll
        for (int w = 0; w < 8; w++) a += shA[w];
        s_bc = 1.f / a;
    }
    __syncthreads();
    float inv = s_bc;
    #pragma unroll
    for (int i = 0; i < 12; i++) po[t + i*256] = __float2bfloat16(x[i] * inv);
}

// cat = [attn | gelu(mlp_in)] -> tripled bf16 A operand for lin2 (h,h,lo)
__global__ void pack_split_kernel() {
    size_t idx = (size_t)blockIdx.x * blockDim.x + threadIdx.x;
    if (idx >= (size_t)LEN * N2) return;
    int l = (int)(idx / N2), c = (int)(idx % N2);
    float val;
    if (c < HID) {
        val = g_attn[((size_t)(c >> 7) * LEN + l) * HD + (c & 127)];
    } else {
        float xx = g_proj[(size_t)l * N1 + 3*HID + (c - HID)];
        float inner = 0.7978845608028654f * (xx + 0.044715f * xx * xx * xx);
        val = 0.5f * xx * (1.f + tanhf(inner));
    }
    __nv_bfloat16 h, lo; split2(val, h, lo);
    size_t o = (size_t)l * K2S + 3*(size_t)c;
    g_a2[o] = h; g_a2[o+1] = h; g_a2[o+2] = lo;
}

__global__ void final_kernel(const float* __restrict__ x, float* __restrict__ out) {
    size_t idx = (size_t)blockIdx.x * blockDim.x + threadIdx.x;
    if (idx >= (size_t)LEN * HID) return;
    int col = (int)(idx % HID);
    out[idx] = x[idx] + g_mod[2*HID + col] * out[idx];
}

// ---------------- launcher ---------------------------------------------------
extern "C" void kernel_launch(void* const* d_in, const int* in_sizes, int n_in,
                              void* d_out, int out_size) {
    const float* x       = (const float*)d_in[0];
    const float* vec     = (const float*)d_in[1];
    const float* pe      = (const float*)d_in[2];
    const float* mod_w   = (const float*)d_in[3];
    const float* mod_b   = (const float*)d_in[4];
    const float* lin1_w  = (const float*)d_in[5];
    const float* lin1_b  = (const float*)d_in[6];
    const float* lin2_w  = (const float*)d_in[7];
    const float* lin2_b  = (const float*)d_in[8];
    const float* q_scale = (const float*)d_in[9];
    const float* k_scale = (const float*)d_in[10];
    float* out = (float*)d_out;

    void *pa1, *pb1, *pa2, *pb2, *pqb, *pkb, *pvT, *pS, *pP, *pattn, *pproj;
    cudaGetSymbolAddress(&pa1, g_a1);   cudaGetSymbolAddress(&pb1, g_b1);
    cudaGetSymbolAddress(&pa2, g_a2);   cudaGetSymbolAddress(&pb2, g_b2);
    cudaGetSymbolAddress(&pqb, g_qb);   cudaGetSymbolAddress(&pkb, g_kb);
    cudaGetSymbolAddress(&pvT, g_vT);   cudaGetSymbolAddress(&pS, g_S);
    cudaGetSymbolAddress(&pP, g_P);     cudaGetSymbolAddress(&pattn, g_attn);
    cudaGetSymbolAddress(&pproj, g_proj);

    const int SMEM = NSTG * STGSZ;   // 61440
    cudaFuncSetAttribute(gemm_hmma, cudaFuncAttributeMaxDynamicSharedMemorySize, SMEM);

    silu_kernel<<<(HID + 255)/256, 256>>>(vec);
    gemv_mod_kernel<<<(3*HID)/8, 256>>>(mod_w, mod_b);
    layernorm_kernel<<<LEN, 256>>>(x);
    conv_w<<<(unsigned)(((size_t)N1*HID + 255)/256), 256>>>(lin1_w, (__nv_bfloat16*)pb1, (size_t)N1*HID);
    conv_w<<<(unsigned)(((size_t)HID*N2 + 255)/256), 256>>>(lin2_w, (__nv_bfloat16*)pb2, (size_t)HID*N2);

    // lin1: M=3072, N=21504, K'=9216
    gemm_hmma<<<dim3(LEN/128, N1/128, 1), 256, SMEM>>>(
        (const __nv_bfloat16*)pa1, (const __nv_bfloat16*)pb1, lin1_b, (float*)pproj,
        N1, K1S, 1.f, 0, 0, 0);

    qkv_prep_kernel<<<(NH*LEN)/8, 256>>>(pe, q_scale, k_scale);

    // QK^T per head: M=N=3072, K'=384, alpha=1/sqrt(128)
    gemm_hmma<<<dim3(LEN/128, LEN/128, NH), 256, SMEM>>>(
        (const __nv_bfloat16*)pqb, (const __nv_bfloat16*)pkb, nullptr, (float*)pS,
        LEN, KQS, 0.08838834764831845f,
        (size_t)LEN*KQS, (size_t)LEN*KQS, (size_t)LEN*LEN);

    softmax_kernel<<<NH*LEN, 256>>>();

    // P@V per head: M=3072, N=128, K=3072
    gemm_hmma<<<dim3(LEN/128, HD/128, NH), 256, SMEM>>>(
        (const __nv_bfloat16*)pP, (const __nv_bfloat16*)pvT, nullptr, (float*)pattn,
        HD, LEN, 1.f,
        (size_t)LEN*LEN, (size_t)HD*LEN, (size_t)LEN*HD);

    pack_split_kernel<<<(unsigned)(((size_t)LEN*N2 + 255)/256), 256>>>();

    // lin2: M=3072, N=3072, K'=46080 -> d_out
    gemm_hmma<<<dim3(LEN/128, HID/128, 1), 256, SMEM>>>(
        (const __nv_bfloat16*)pa2, (const __nv_bfloat16*)pb2, lin2_b, out,
        HID, K2S, 1.f, 0, 0, 0);

    final_kernel<<<(unsigned)(((size_t)LEN*HID + 255)/256), 256>>>(x, out);
}